// round 12
// baseline (speedup 1.0000x reference)
#include <cuda_runtime.h>
#include <cuda_fp16.h>
#include <cstdint>

#define N_NODES 100000
#define N_EDGES 1600000
#define FDIM    128
#define CONCAT  512            // (K+1)*128

// ---------------- static scratch (allocation-free) ----------------
__device__ int     g_cnt[N_NODES];
__device__ int     g_row[N_NODES + 1];
__device__ int     g_cur[N_NODES];
__device__ int     g_bsum[256];                      // 196 used
__device__ int     g_csr_src[N_EDGES];
__device__ float   g_norm[N_NODES];
// fp16 message buffers, one per hop slot: [N][128] halfs = 16 uint4 per node
// invariant: msg_s[m] = feats_s[m] * nm[m]
__device__ uint4   g_msg0[(size_t)N_NODES * 16];
__device__ uint4   g_msg1[(size_t)N_NODES * 16];
__device__ uint4   g_msg2[(size_t)N_NODES * 16];
__device__ uint4   g_msg3[(size_t)N_NODES * 16];
// W transposed to [n][k], fp16 hi/lo split
__device__ __align__(16) __half g_Wh1[128 * 512];
__device__ __align__(16) __half g_Wl1[128 * 512];
__device__ __align__(16) __half g_Wh2[128 * 512];
__device__ __align__(16) __half g_Wl2[128 * 512];

__device__ __forceinline__ void add8(float* a, uint4 u) {
    float2 p0 = __half22float2(*(__half2*)&u.x);
    float2 p1 = __half22float2(*(__half2*)&u.y);
    float2 p2 = __half22float2(*(__half2*)&u.z);
    float2 p3 = __half22float2(*(__half2*)&u.w);
    a[0] += p0.x; a[1] += p0.y; a[2] += p1.x; a[3] += p1.y;
    a[4] += p2.x; a[5] += p2.y; a[6] += p3.x; a[7] += p3.y;
}
__device__ __forceinline__ uint4 h2add8(uint4 a, uint4 b) {
    uint4 r;
    *(__half2*)&r.x = __hadd2(*(__half2*)&a.x, *(__half2*)&b.x);
    *(__half2*)&r.y = __hadd2(*(__half2*)&a.y, *(__half2*)&b.y);
    *(__half2*)&r.z = __hadd2(*(__half2*)&a.z, *(__half2*)&b.z);
    *(__half2*)&r.w = __hadd2(*(__half2*)&a.w, *(__half2*)&b.w);
    return r;
}
__device__ __forceinline__ uint4 pack8(const float* a, float s) {
    __half2 h0 = __floats2half2_rn(a[0] * s, a[1] * s);
    __half2 h1 = __floats2half2_rn(a[2] * s, a[3] * s);
    __half2 h2 = __floats2half2_rn(a[4] * s, a[5] * s);
    __half2 h3 = __floats2half2_rn(a[6] * s, a[7] * s);
    uint4 u;
    u.x = *(uint32_t*)&h0; u.y = *(uint32_t*)&h1;
    u.z = *(uint32_t*)&h2; u.w = *(uint32_t*)&h3;
    return u;
}
__device__ __forceinline__ uint32_t s2u(const void* p) {
    uint32_t a;
    asm("{ .reg .u64 t; cvta.to.shared.u64 t, %1; cvt.u32.u64 %0, t; }" : "=r"(a) : "l"(p));
    return a;
}
__device__ __forceinline__ void ldsm4(uint32_t* r, uint32_t addr) {
    asm volatile("ldmatrix.sync.aligned.m8n8.x4.shared.b16 {%0,%1,%2,%3}, [%4];"
                 : "=r"(r[0]), "=r"(r[1]), "=r"(r[2]), "=r"(r[3]) : "r"(addr));
}
__device__ __forceinline__ void mma16816(float* c, const uint32_t* a, const uint32_t* b) {
    asm volatile(
        "mma.sync.aligned.m16n8k16.row.col.f32.f16.f16.f32 "
        "{%0,%1,%2,%3}, {%4,%5,%6,%7}, {%8,%9}, {%0,%1,%2,%3};"
        : "+f"(c[0]), "+f"(c[1]), "+f"(c[2]), "+f"(c[3])
        : "r"(a[0]), "r"(a[1]), "r"(a[2]), "r"(a[3]), "r"(b[0]), "r"(b[1]));
}

// ---------------- CSR build ----------------
__global__ void k_hist(const int* __restrict__ dst) {
    int e = blockIdx.x * blockDim.x + threadIdx.x;
    if (e < N_EDGES) atomicAdd(&g_cnt[dst[e]], 1);
}

#define SCAN_T 512
#define SCAN_NB ((N_NODES + SCAN_T - 1) / SCAN_T)   // 196

__global__ void k_scan1() {
    __shared__ int sh[SCAN_T];
    int tid = threadIdx.x;
    int gi  = blockIdx.x * SCAN_T + tid;
    int v   = (gi < N_NODES) ? g_cnt[gi] : 0;
    if (gi < N_NODES) {
        int d = v < 1 ? 1 : v;
        g_norm[gi] = rsqrtf((float)d);
    }
    sh[tid] = v;
    __syncthreads();
    for (int off = 1; off < SCAN_T; off <<= 1) {
        int t = (tid >= off) ? sh[tid - off] : 0;
        __syncthreads();
        sh[tid] += t;
        __syncthreads();
    }
    if (gi < N_NODES) g_row[gi] = sh[tid] - v;
    if (tid == SCAN_T - 1) g_bsum[blockIdx.x] = sh[tid];
}

__global__ void k_scan3() {
    __shared__ int s_off;
    int tid = threadIdx.x;
    int bid = blockIdx.x;
    if (tid < 32) {
        int s = 0;
        for (int i = tid; i < bid; i += 32) s += g_bsum[i];
#pragma unroll
        for (int o = 16; o > 0; o >>= 1) s += __shfl_down_sync(0xFFFFFFFF, s, o);
        if (tid == 0) s_off = s;
    }
    __syncthreads();
    int gi = bid * SCAN_T + tid;
    if (gi < N_NODES) {
        int v = g_row[gi] + s_off;
        g_row[gi] = v;
        g_cur[gi] = v;
    }
    if (gi == 0) g_row[N_NODES] = N_EDGES;
}

__global__ void k_fill(const int* __restrict__ src, const int* __restrict__ dst) {
    int e = blockIdx.x * blockDim.x + threadIdx.x;
    if (e < N_EDGES) {
        int d   = dst[e];
        int pos = atomicAdd(&g_cur[d], 1);
        g_csr_src[pos] = src[e];
    }
}

// ---------------- W prep: transpose + fp16 hi/lo split ----------------
__global__ void k_prepW(const float* __restrict__ W1, const float* __restrict__ W2) {
    int idx = blockIdx.x * blockDim.x + threadIdx.x;   // 512*128
    if (idx >= 512 * 128) return;
    int k = idx >> 7;
    int n = idx & 127;
    float w1 = W1[idx];
    __half h1 = __float2half_rn(w1);
    g_Wh1[n * 512 + k] = h1;
    g_Wl1[n * 512 + k] = __float2half_rn(w1 - __half2float(h1));
    float w2 = W2[idx];
    __half h2 = __float2half_rn(w2);
    g_Wh2[n * 512 + k] = h2;
    g_Wl2[n * 512 + k] = __float2half_rn(w2 - __half2float(h2));
}

// ---------------- copy x -> msg0 = x * nm (fp16) ----------------
__global__ void k_copy0(const float4* __restrict__ x4) {
    int idx = blockIdx.x * blockDim.x + threadIdx.x;   // N*16
    int node = idx >> 4;
    int q    = idx & 15;
    float4 v0 = x4[node * 32 + q * 2];
    float4 v1 = x4[node * 32 + q * 2 + 1];
    float a[8] = {v0.x, v0.y, v0.z, v0.w, v1.x, v1.y, v1.z, v1.w};
    g_msg0[(size_t)node * 16 + q] = pack8(a, g_norm[node]);
}

// ---------------- aggregation: ONE WARP per node, even/odd group split ----------------
// lanes 0-15 take even 4-edge groups, lanes 16-31 odd groups; shfl_xor(16) combine.
// out[m] = (sum_{e in row m} in[src]) * nm[m]^2
__global__ __launch_bounds__(256) void k_agg(const uint4* __restrict__ tin,
                                             uint4* __restrict__ tout) {
    int wid  = threadIdx.x >> 5;                       // 0..7
    int lane = threadIdx.x & 31;
    int half = lane >> 4;                              // 0 or 1
    int hl   = lane & 15;
    int node = blockIdx.x * 8 + wid;                   // grid = 12500, exact

    int beg = g_row[node];
    int end = g_row[node + 1];

    float acc[8] = {0.f, 0.f, 0.f, 0.f, 0.f, 0.f, 0.f, 0.f};

    // head (to 4-alignment): lanes 0-15 only
    int e = beg;
    int alignEnd = (beg + 3) & ~3;
    if (alignEnd > end) alignEnd = end;
    if (half == 0) {
        for (int t = e; t < alignEnd; t++) {
            int s = __ldg(&g_csr_src[t]);
            add8(acc, tin[(size_t)s * 16 + hl]);
        }
    }
    e = alignEnd;

    // main: half h takes groups h, h+2, h+4, ... (8 gathers in flight per warp)
    int ng = (end - e) >> 2;
    for (int g = half; g < ng; g += 2) {
        int4 s4 = *(const int4*)&g_csr_src[e + (g << 2)];
        uint4 u0 = tin[(size_t)s4.x * 16 + hl];
        uint4 u1 = tin[(size_t)s4.y * 16 + hl];
        uint4 u2 = tin[(size_t)s4.z * 16 + hl];
        uint4 u3 = tin[(size_t)s4.w * 16 + hl];
        uint4 q = h2add8(h2add8(u0, u1), h2add8(u2, u3));
        add8(acc, q);
    }
    e += ng << 2;

    // tail (<4 edges): lanes 16-31 only
    if (half == 1) {
        for (int t = e; t < end; t++) {
            int s = __ldg(&g_csr_src[t]);
            add8(acc, tin[(size_t)s * 16 + hl]);
        }
    }

    // combine halves
#pragma unroll
    for (int i = 0; i < 8; i++)
        acc[i] += __shfl_xor_sync(0xFFFFFFFF, acc[i], 16);

    if (half == 0) {
        float nm = g_norm[node];
        tout[(size_t)node * 16 + hl] = pack8(acc, nm * nm);
    }
}

// ---------------- HMMA GEMM: relu((msgcat[M,512] @ W) / nm + b) ----------------
// Block tile 128x128, 256 threads = 4(M) x 2(N) warps, each warp 32x64.  (R9-proven)
#define ASTRIDE 80
__global__ __launch_bounds__(256) void k_gemm_mma(const __half* __restrict__ m0,
                                                  const __half* __restrict__ m1,
                                                  const __half* __restrict__ m2,
                                                  const __half* __restrict__ m3,
                                                  const __half* __restrict__ Wh,
                                                  const __half* __restrict__ Wl,
                                                  const float* __restrict__ bias,
                                                  float* __restrict__ out,
                                                  int mode) {
    __shared__ __align__(16) char sA [128 * ASTRIDE];
    __shared__ __align__(16) char sBh[128 * ASTRIDE];
    __shared__ __align__(16) char sBl[128 * ASTRIDE];
    __shared__ float sBias[128];

    int tid  = threadIdx.x;
    int lane = tid & 31;
    int wid  = tid >> 5;
    int wm   = wid & 3;
    int wn   = wid >> 2;
    int row0 = blockIdx.x * 128;

    if (tid < 128) sBias[tid] = bias[tid];

    uint32_t aA = s2u(sA), aBh = s2u(sBh), aBl = s2u(sBl);

    uint32_t aRow = (lane & 7) + ((lane >> 3) & 1) * 8;
    uint32_t aCol = (lane >> 4) * 16;
    uint32_t bRow = (lane & 7) + (lane >> 4) * 8;
    uint32_t bCol = ((lane >> 3) & 1) * 16;

    float acc[2][8][4];
#pragma unroll
    for (int mt = 0; mt < 2; mt++)
#pragma unroll
        for (int nt = 0; nt < 8; nt++)
#pragma unroll
            for (int q = 0; q < 4; q++) acc[mt][nt][q] = 0.f;

    int fr0 = tid >> 2,         fq0 = tid & 3;
    int fr1 = (tid + 256) >> 2, fq1 = (tid + 256) & 3;
    int grow0 = row0 + fr0; if (grow0 > N_NODES - 1) grow0 = N_NODES - 1;
    int grow1 = row0 + fr1; if (grow1 > N_NODES - 1) grow1 = N_NODES - 1;

    for (int kc = 0; kc < 16; kc++) {
        const __half* M = (kc < 8) ? ((kc < 4) ? m0 : m1) : ((kc < 12) ? m2 : m3);
        int ko = (kc & 3) * 32;
        {
            uint4 v0 = *((const uint4*)(M + (size_t)grow0 * FDIM + ko) + fq0);
            uint4 v1 = *((const uint4*)(M + (size_t)grow1 * FDIM + ko) + fq1);
            *(uint4*)(sA + fr0 * ASTRIDE + fq0 * 16) = v0;
            *(uint4*)(sA + fr1 * ASTRIDE + fq1 * 16) = v1;
        }
#pragma unroll
        for (int jj = 0; jj < 2; jj++) {
            int f = jj * 256 + tid;
            int r = f >> 2;
            int s = f & 3;
            size_t go = ((size_t)r * 512 + kc * 32) * 2 + s * 16;
            *(uint4*)(sBh + r * ASTRIDE + s * 16) = *(const uint4*)((const char*)Wh + go);
            *(uint4*)(sBl + r * ASTRIDE + s * 16) = *(const uint4*)((const char*)Wl + go);
        }
        __syncthreads();

#pragma unroll
        for (int ks = 0; ks < 2; ks++) {
            uint32_t kb = ks * 32;
            uint32_t ah[2][4];
#pragma unroll
            for (int mt = 0; mt < 2; mt++) {
                uint32_t row = wm * 32 + mt * 16 + aRow;
                ldsm4(ah[mt], aA + row * ASTRIDE + kb + aCol);
            }
            uint32_t bh[4][4], bl[4][4];
#pragma unroll
            for (int np = 0; np < 4; np++) {
                uint32_t row = wn * 64 + np * 16 + bRow;
                ldsm4(bh[np], aBh + row * ASTRIDE + kb + bCol);
                ldsm4(bl[np], aBl + row * ASTRIDE + kb + bCol);
            }
#pragma unroll
            for (int mt = 0; mt < 2; mt++)
#pragma unroll
                for (int nt = 0; nt < 8; nt++) {
                    const uint32_t* fh = &bh[nt >> 1][(nt & 1) * 2];
                    const uint32_t* fl = &bl[nt >> 1][(nt & 1) * 2];
                    float* c = acc[mt][nt];
                    mma16816(c, ah[mt], fh);   // A*Whi
                    mma16816(c, ah[mt], fl);   // A*Wlo
                }
        }
        __syncthreads();
    }

    // --- epilogue: unscale by 1/nm, bias, relu, fused stores ---
    int qr = lane >> 2;
    int qc = lane & 3;
#pragma unroll
    for (int mt = 0; mt < 2; mt++) {
#pragma unroll
        for (int half = 0; half < 2; half++) {
            int m = row0 + wm * 32 + mt * 16 + qr + half * 8;
            if (m >= N_NODES) continue;
            float nm  = g_norm[m];
            float rnm = 1.0f / nm;
            uint32_t* mrow = (uint32_t*)g_msg0 + (size_t)m * 64;
            float*    orow = out + (size_t)m * FDIM;
#pragma unroll
            for (int nt = 0; nt < 8; nt++) {
                int col = wn * 64 + nt * 8 + qc * 2;
                float c0 = acc[mt][nt][half * 2 + 0] * rnm + sBias[col];
                float c1 = acc[mt][nt][half * 2 + 1] * rnm + sBias[col + 1];
                c0 = c0 > 0.f ? c0 : 0.f;
                c1 = c1 > 0.f ? c1 : 0.f;
                if (mode == 1) {
                    __half2 t = __floats2half2_rn(c0 * nm, c1 * nm);
                    mrow[col >> 1] = *(uint32_t*)&t;   // msg0 for layer 2
                } else {
                    *(float2*)(orow + col) = make_float2(c0, c1);
                }
            }
        }
    }
}

// ---------------- launch ----------------
extern "C" void kernel_launch(void* const* d_in, const int* in_sizes, int n_in,
                              void* d_out, int out_size) {
    const float* x  = (const float*)d_in[0];
    const int*   ei = (const int*)  d_in[1];
    const float* W1 = (const float*)d_in[2];
    const float* b1 = (const float*)d_in[3];
    const float* W2 = (const float*)d_in[4];
    const float* b2 = (const float*)d_in[5];
    float* out = (float*)d_out;

    const int* src = ei;
    const int* dst = ei + N_EDGES;

    const int TB = 256;
    const int gE = (N_EDGES + TB - 1) / TB;

    __half *wh1, *wl1, *wh2, *wl2;
    uint4 *p0, *p1, *p2, *p3;
    int* cnt;
    cudaGetSymbolAddress((void**)&wh1, g_Wh1);
    cudaGetSymbolAddress((void**)&wl1, g_Wl1);
    cudaGetSymbolAddress((void**)&wh2, g_Wh2);
    cudaGetSymbolAddress((void**)&wl2, g_Wl2);
    cudaGetSymbolAddress((void**)&p0, g_msg0);
    cudaGetSymbolAddress((void**)&p1, g_msg1);
    cudaGetSymbolAddress((void**)&p2, g_msg2);
    cudaGetSymbolAddress((void**)&p3, g_msg3);
    cudaGetSymbolAddress((void**)&cnt, g_cnt);

    // --- CSR-by-dst build + norms + W prep ---
    cudaMemsetAsync(cnt, 0, N_NODES * sizeof(int));
    k_hist<<<gE, TB>>>(dst);
    k_scan1<<<SCAN_NB, SCAN_T>>>();       // also computes g_norm
    k_scan3<<<SCAN_NB, SCAN_T>>>();       // block-prefix computed in-block
    k_fill<<<gE, TB>>>(src, dst);
    k_prepW<<<(512 * 128) / TB, TB>>>(W1, W2);

    const int gAgg  = N_NODES / 8;                      // 12500 (warp per node)
    const int gCpy  = (N_NODES * 16) / TB;              // 6250
    const int gGemm = (N_NODES + 127) / 128;            // 782

    // --- layer 1 ---
    k_copy0<<<gCpy, TB>>>((const float4*)x);
    k_agg<<<gAgg, TB>>>(p0, p1);
    k_agg<<<gAgg, TB>>>(p1, p2);
    k_agg<<<gAgg, TB>>>(p2, p3);
    k_gemm_mma<<<gGemm, TB>>>((const __half*)p0, (const __half*)p1, (const __half*)p2,
                              (const __half*)p3, wh1, wl1, b1, nullptr, 1);

    // --- layer 2 ---
    k_agg<<<gAgg, TB>>>(p0, p1);
    k_agg<<<gAgg, TB>>>(p1, p2);
    k_agg<<<gAgg, TB>>>(p2, p3);
    k_gemm_mma<<<gGemm, TB>>>((const __half*)p0, (const __half*)p1, (const __half*)p2,
                              (const __half*)p3, wh2, wl2, b2, out, 2);
}

// round 15
// speedup vs baseline: 1.2433x; 1.2433x over previous
#include <cuda_runtime.h>
#include <cuda_fp16.h>
#include <cstdint>

#define N_NODES 100000
#define N_EDGES 1600000
#define FDIM    128
#define CONCAT  512            // (K+1)*128

// ---------------- static scratch (allocation-free) ----------------
__device__ int     g_cnt[N_NODES];
__device__ int     g_row[N_NODES + 1];
__device__ int     g_cur[N_NODES];
__device__ int     g_bsum[256];                      // 196 used
__device__ int     g_csr_src[N_EDGES];
__device__ float   g_norm[N_NODES];
// fp16 message buffers, one per hop slot: [N][128] halfs = 16 uint4 per node
// invariant: msg_s[m] = feats_s[m] * nm[m]
__device__ uint4   g_msg0[(size_t)N_NODES * 16];
__device__ uint4   g_msg1[(size_t)N_NODES * 16];
__device__ uint4   g_msg2[(size_t)N_NODES * 16];
__device__ uint4   g_msg3[(size_t)N_NODES * 16];
// W transposed to [n][k], fp16 hi/lo split
__device__ __align__(16) __half g_Wh1[128 * 512];
__device__ __align__(16) __half g_Wl1[128 * 512];
__device__ __align__(16) __half g_Wh2[128 * 512];
__device__ __align__(16) __half g_Wl2[128 * 512];

__device__ __forceinline__ void add8(float* a, uint4 u) {
    float2 p0 = __half22float2(*(__half2*)&u.x);
    float2 p1 = __half22float2(*(__half2*)&u.y);
    float2 p2 = __half22float2(*(__half2*)&u.z);
    float2 p3 = __half22float2(*(__half2*)&u.w);
    a[0] += p0.x; a[1] += p0.y; a[2] += p1.x; a[3] += p1.y;
    a[4] += p2.x; a[5] += p2.y; a[6] += p3.x; a[7] += p3.y;
}
__device__ __forceinline__ uint4 h2add8(uint4 a, uint4 b) {
    uint4 r;
    *(__half2*)&r.x = __hadd2(*(__half2*)&a.x, *(__half2*)&b.x);
    *(__half2*)&r.y = __hadd2(*(__half2*)&a.y, *(__half2*)&b.y);
    *(__half2*)&r.z = __hadd2(*(__half2*)&a.z, *(__half2*)&b.z);
    *(__half2*)&r.w = __hadd2(*(__half2*)&a.w, *(__half2*)&b.w);
    return r;
}
__device__ __forceinline__ uint4 pack8(const float* a, float s) {
    __half2 h0 = __floats2half2_rn(a[0] * s, a[1] * s);
    __half2 h1 = __floats2half2_rn(a[2] * s, a[3] * s);
    __half2 h2 = __floats2half2_rn(a[4] * s, a[5] * s);
    __half2 h3 = __floats2half2_rn(a[6] * s, a[7] * s);
    uint4 u;
    u.x = *(uint32_t*)&h0; u.y = *(uint32_t*)&h1;
    u.z = *(uint32_t*)&h2; u.w = *(uint32_t*)&h3;
    return u;
}
__device__ __forceinline__ uint32_t s2u(const void* p) {
    uint32_t a;
    asm("{ .reg .u64 t; cvta.to.shared.u64 t, %1; cvt.u32.u64 %0, t; }" : "=r"(a) : "l"(p));
    return a;
}
__device__ __forceinline__ void ldsm4(uint32_t* r, uint32_t addr) {
    asm volatile("ldmatrix.sync.aligned.m8n8.x4.shared.b16 {%0,%1,%2,%3}, [%4];"
                 : "=r"(r[0]), "=r"(r[1]), "=r"(r[2]), "=r"(r[3]) : "r"(addr));
}
__device__ __forceinline__ void mma16816(float* c, const uint32_t* a, const uint32_t* b) {
    asm volatile(
        "mma.sync.aligned.m16n8k16.row.col.f32.f16.f16.f32 "
        "{%0,%1,%2,%3}, {%4,%5,%6,%7}, {%8,%9}, {%0,%1,%2,%3};"
        : "+f"(c[0]), "+f"(c[1]), "+f"(c[2]), "+f"(c[3])
        : "r"(a[0]), "r"(a[1]), "r"(a[2]), "r"(a[3]), "r"(b[0]), "r"(b[1]));
}

// ---------------- CSR build ----------------
__global__ void k_hist(const int* __restrict__ dst) {
    int e = blockIdx.x * blockDim.x + threadIdx.x;
    if (e < N_EDGES) atomicAdd(&g_cnt[dst[e]], 1);
}

#define SCAN_T 512
#define SCAN_NB ((N_NODES + SCAN_T - 1) / SCAN_T)   // 196

__global__ void k_scan1() {
    __shared__ int sh[SCAN_T];
    int tid = threadIdx.x;
    int gi  = blockIdx.x * SCAN_T + tid;
    int v   = (gi < N_NODES) ? g_cnt[gi] : 0;
    if (gi < N_NODES) {
        int d = v < 1 ? 1 : v;
        g_norm[gi] = rsqrtf((float)d);
    }
    sh[tid] = v;
    __syncthreads();
    for (int off = 1; off < SCAN_T; off <<= 1) {
        int t = (tid >= off) ? sh[tid - off] : 0;
        __syncthreads();
        sh[tid] += t;
        __syncthreads();
    }
    if (gi < N_NODES) g_row[gi] = sh[tid] - v;
    if (tid == SCAN_T - 1) g_bsum[blockIdx.x] = sh[tid];
}

__global__ void k_scan3() {
    __shared__ int s_off;
    int tid = threadIdx.x;
    int bid = blockIdx.x;
    if (tid < 32) {
        int s = 0;
        for (int i = tid; i < bid; i += 32) s += g_bsum[i];
#pragma unroll
        for (int o = 16; o > 0; o >>= 1) s += __shfl_down_sync(0xFFFFFFFF, s, o);
        if (tid == 0) s_off = s;
    }
    __syncthreads();
    int gi = bid * SCAN_T + tid;
    if (gi < N_NODES) {
        int v = g_row[gi] + s_off;
        g_row[gi] = v;
        g_cur[gi] = v;
    }
    if (gi == 0) g_row[N_NODES] = N_EDGES;
}

__global__ void k_fill(const int* __restrict__ src, const int* __restrict__ dst) {
    int e = blockIdx.x * blockDim.x + threadIdx.x;
    if (e < N_EDGES) {
        int d   = dst[e];
        int pos = atomicAdd(&g_cur[d], 1);
        g_csr_src[pos] = src[e];
    }
}

// ---------------- W prep: transpose + fp16 hi/lo split ----------------
__global__ void k_prepW(const float* __restrict__ W1, const float* __restrict__ W2) {
    int idx = blockIdx.x * blockDim.x + threadIdx.x;   // 512*128
    if (idx >= 512 * 128) return;
    int k = idx >> 7;
    int n = idx & 127;
    float w1 = W1[idx];
    __half h1 = __float2half_rn(w1);
    g_Wh1[n * 512 + k] = h1;
    g_Wl1[n * 512 + k] = __float2half_rn(w1 - __half2float(h1));
    float w2 = W2[idx];
    __half h2 = __float2half_rn(w2);
    g_Wh2[n * 512 + k] = h2;
    g_Wl2[n * 512 + k] = __float2half_rn(w2 - __half2float(h2));
}

// ---------------- copy x -> msg0 = x * nm (fp16) ----------------
__global__ void k_copy0(const float4* __restrict__ x4) {
    int idx = blockIdx.x * blockDim.x + threadIdx.x;   // N*16
    int node = idx >> 4;
    int q    = idx & 15;
    float4 v0 = x4[node * 32 + q * 2];
    float4 v1 = x4[node * 32 + q * 2 + 1];
    float a[8] = {v0.x, v0.y, v0.z, v0.w, v1.x, v1.y, v1.z, v1.w};
    g_msg0[(size_t)node * 16 + q] = pack8(a, g_norm[node]);
}

// ---------------- aggregation: half-warp per node, fp16 quad-tree sums ----------------
// out[m] = (sum_{e in row m} in[src]) * nm[m]^2       (R9-proven layout)
__global__ __launch_bounds__(256) void k_agg(const uint4* __restrict__ tin,
                                             uint4* __restrict__ tout) {
    int hw   = threadIdx.x >> 4;                       // 0..15
    int hl   = threadIdx.x & 15;
    int node = blockIdx.x * 16 + hw;                   // grid = 6250, exact

    int beg = g_row[node];
    int end = g_row[node + 1];

    float acc[8] = {0.f, 0.f, 0.f, 0.f, 0.f, 0.f, 0.f, 0.f};

    // head: advance to 4-aligned edge index
    int e = beg;
    int alignEnd = (beg + 3) & ~3;
    if (alignEnd > end) alignEnd = end;
    for (; e < alignEnd; e++) {
        int s = __ldg(&g_csr_src[e]);
        add8(acc, tin[(size_t)s * 16 + hl]);
    }
    // main: 4 edges per iter, vector index load + fp16 quad tree
    for (; e + 4 <= end; e += 4) {
        int4 s4 = *(const int4*)&g_csr_src[e];         // 16B aligned
        uint4 u0 = tin[(size_t)s4.x * 16 + hl];
        uint4 u1 = tin[(size_t)s4.y * 16 + hl];
        uint4 u2 = tin[(size_t)s4.z * 16 + hl];
        uint4 u3 = tin[(size_t)s4.w * 16 + hl];
        uint4 q = h2add8(h2add8(u0, u1), h2add8(u2, u3));
        add8(acc, q);
    }
    // tail
    for (; e < end; e++) {
        int s = __ldg(&g_csr_src[e]);
        add8(acc, tin[(size_t)s * 16 + hl]);
    }

    float nm = g_norm[node];
    tout[(size_t)node * 16 + hl] = pack8(acc, nm * nm);
}

// ---------------- HMMA GEMM: relu((msgcat[M,512] @ W) / nm + b) ----------------
// Block tile 128x128, 256 threads = 4(M) x 2(N) warps, each warp 32x64.  (R9-proven)
#define ASTRIDE 80
__global__ __launch_bounds__(256) void k_gemm_mma(const __half* __restrict__ m0,
                                                  const __half* __restrict__ m1,
                                                  const __half* __restrict__ m2,
                                                  const __half* __restrict__ m3,
                                                  const __half* __restrict__ Wh,
                                                  const __half* __restrict__ Wl,
                                                  const float* __restrict__ bias,
                                                  float* __restrict__ out,
                                                  int mode) {
    __shared__ __align__(16) char sA [128 * ASTRIDE];
    __shared__ __align__(16) char sBh[128 * ASTRIDE];
    __shared__ __align__(16) char sBl[128 * ASTRIDE];
    __shared__ float sBias[128];

    int tid  = threadIdx.x;
    int lane = tid & 31;
    int wid  = tid >> 5;
    int wm   = wid & 3;
    int wn   = wid >> 2;
    int row0 = blockIdx.x * 128;

    if (tid < 128) sBias[tid] = bias[tid];

    uint32_t aA = s2u(sA), aBh = s2u(sBh), aBl = s2u(sBl);

    uint32_t aRow = (lane & 7) + ((lane >> 3) & 1) * 8;
    uint32_t aCol = (lane >> 4) * 16;
    uint32_t bRow = (lane & 7) + (lane >> 4) * 8;
    uint32_t bCol = ((lane >> 3) & 1) * 16;

    float acc[2][8][4];
#pragma unroll
    for (int mt = 0; mt < 2; mt++)
#pragma unroll
        for (int nt = 0; nt < 8; nt++)
#pragma unroll
            for (int q = 0; q < 4; q++) acc[mt][nt][q] = 0.f;

    int fr0 = tid >> 2,         fq0 = tid & 3;
    int fr1 = (tid + 256) >> 2, fq1 = (tid + 256) & 3;
    int grow0 = row0 + fr0; if (grow0 > N_NODES - 1) grow0 = N_NODES - 1;
    int grow1 = row0 + fr1; if (grow1 > N_NODES - 1) grow1 = N_NODES - 1;

    for (int kc = 0; kc < 16; kc++) {
        const __half* M = (kc < 8) ? ((kc < 4) ? m0 : m1) : ((kc < 12) ? m2 : m3);
        int ko = (kc & 3) * 32;
        {
            uint4 v0 = *((const uint4*)(M + (size_t)grow0 * FDIM + ko) + fq0);
            uint4 v1 = *((const uint4*)(M + (size_t)grow1 * FDIM + ko) + fq1);
            *(uint4*)(sA + fr0 * ASTRIDE + fq0 * 16) = v0;
            *(uint4*)(sA + fr1 * ASTRIDE + fq1 * 16) = v1;
        }
#pragma unroll
        for (int jj = 0; jj < 2; jj++) {
            int f = jj * 256 + tid;
            int r = f >> 2;
            int s = f & 3;
            size_t go = ((size_t)r * 512 + kc * 32) * 2 + s * 16;
            *(uint4*)(sBh + r * ASTRIDE + s * 16) = *(const uint4*)((const char*)Wh + go);
            *(uint4*)(sBl + r * ASTRIDE + s * 16) = *(const uint4*)((const char*)Wl + go);
        }
        __syncthreads();

#pragma unroll
        for (int ks = 0; ks < 2; ks++) {
            uint32_t kb = ks * 32;
            uint32_t ah[2][4];
#pragma unroll
            for (int mt = 0; mt < 2; mt++) {
                uint32_t row = wm * 32 + mt * 16 + aRow;
                ldsm4(ah[mt], aA + row * ASTRIDE + kb + aCol);
            }
            uint32_t bh[4][4], bl[4][4];
#pragma unroll
            for (int np = 0; np < 4; np++) {
                uint32_t row = wn * 64 + np * 16 + bRow;
                ldsm4(bh[np], aBh + row * ASTRIDE + kb + bCol);
                ldsm4(bl[np], aBl + row * ASTRIDE + kb + bCol);
            }
#pragma unroll
            for (int mt = 0; mt < 2; mt++)
#pragma unroll
                for (int nt = 0; nt < 8; nt++) {
                    const uint32_t* fh = &bh[nt >> 1][(nt & 1) * 2];
                    const uint32_t* fl = &bl[nt >> 1][(nt & 1) * 2];
                    float* c = acc[mt][nt];
                    mma16816(c, ah[mt], fh);   // A*Whi
                    mma16816(c, ah[mt], fl);   // A*Wlo
                }
        }
        __syncthreads();
    }

    // --- epilogue: unscale by 1/nm, bias, relu, fused stores ---
    int qr = lane >> 2;
    int qc = lane & 3;
#pragma unroll
    for (int mt = 0; mt < 2; mt++) {
#pragma unroll
        for (int half = 0; half < 2; half++) {
            int m = row0 + wm * 32 + mt * 16 + qr + half * 8;
            if (m >= N_NODES) continue;
            float nm  = g_norm[m];
            float rnm = 1.0f / nm;
            uint32_t* mrow = (uint32_t*)g_msg0 + (size_t)m * 64;
            float*    orow = out + (size_t)m * FDIM;
#pragma unroll
            for (int nt = 0; nt < 8; nt++) {
                int col = wn * 64 + nt * 8 + qc * 2;
                float c0 = acc[mt][nt][half * 2 + 0] * rnm + sBias[col];
                float c1 = acc[mt][nt][half * 2 + 1] * rnm + sBias[col + 1];
                c0 = c0 > 0.f ? c0 : 0.f;
                c1 = c1 > 0.f ? c1 : 0.f;
                if (mode == 1) {
                    __half2 t = __floats2half2_rn(c0 * nm, c1 * nm);
                    mrow[col >> 1] = *(uint32_t*)&t;   // msg0 for layer 2
                } else {
                    *(float2*)(orow + col) = make_float2(c0, c1);
                }
            }
        }
    }
}

// ---------------- launch ----------------
extern "C" void kernel_launch(void* const* d_in, const int* in_sizes, int n_in,
                              void* d_out, int out_size) {
    const float* x  = (const float*)d_in[0];
    const int*   ei = (const int*)  d_in[1];
    const float* W1 = (const float*)d_in[2];
    const float* b1 = (const float*)d_in[3];
    const float* W2 = (const float*)d_in[4];
    const float* b2 = (const float*)d_in[5];
    float* out = (float*)d_out;

    const int* src = ei;
    const int* dst = ei + N_EDGES;

    const int TB = 256;
    const int gE = (N_EDGES + TB - 1) / TB;

    __half *wh1, *wl1, *wh2, *wl2;
    uint4 *p0, *p1, *p2, *p3;
    int* cnt;
    cudaGetSymbolAddress((void**)&wh1, g_Wh1);
    cudaGetSymbolAddress((void**)&wl1, g_Wl1);
    cudaGetSymbolAddress((void**)&wh2, g_Wh2);
    cudaGetSymbolAddress((void**)&wl2, g_Wl2);
    cudaGetSymbolAddress((void**)&p0, g_msg0);
    cudaGetSymbolAddress((void**)&p1, g_msg1);
    cudaGetSymbolAddress((void**)&p2, g_msg2);
    cudaGetSymbolAddress((void**)&p3, g_msg3);
    cudaGetSymbolAddress((void**)&cnt, g_cnt);

    // --- CSR-by-dst build + norms + W prep ---
    cudaMemsetAsync(cnt, 0, N_NODES * sizeof(int));
    k_hist<<<gE, TB>>>(dst);
    k_scan1<<<SCAN_NB, SCAN_T>>>();       // also computes g_norm
    k_scan3<<<SCAN_NB, SCAN_T>>>();       // block-prefix computed in-block
    k_fill<<<gE, TB>>>(src, dst);
    k_prepW<<<(512 * 128) / TB, TB>>>(W1, W2);

    const int gAgg  = N_NODES / 16;                     // 6250 (half-warp per node)
    const int gCpy  = (N_NODES * 16) / TB;              // 6250
    const int gGemm = (N_NODES + 127) / 128;            // 782

    // --- layer 1 ---
    k_copy0<<<gCpy, TB>>>((const float4*)x);
    k_agg<<<gAgg, TB>>>(p0, p1);
    k_agg<<<gAgg, TB>>>(p1, p2);
    k_agg<<<gAgg, TB>>>(p2, p3);
    k_gemm_mma<<<gGemm, TB>>>((const __half*)p0, (const __half*)p1, (const __half*)p2,
                              (const __half*)p3, wh1, wl1, b1, nullptr, 1);

    // --- layer 2 ---
    k_agg<<<gAgg, TB>>>(p0, p1);
    k_agg<<<gAgg, TB>>>(p1, p2);
    k_agg<<<gAgg, TB>>>(p2, p3);
    k_gemm_mma<<<gGemm, TB>>>((const __half*)p0, (const __half*)p1, (const __half*)p2,
                              (const __half*)p3, wh2, wl2, b2, out, 2);
}

// round 16
// speedup vs baseline: 1.4788x; 1.1895x over previous
#include <cuda_runtime.h>
#include <cuda_fp16.h>
#include <cstdint>

#define N_NODES 100000
#define N_EDGES 1600000
#define FDIM    128
#define CONCAT  512            // (K+1)*128

// ---------------- static scratch (allocation-free) ----------------
__device__ int     g_cnt[N_NODES];
__device__ int     g_row[N_NODES + 1];
__device__ int     g_cur[N_NODES];
__device__ int     g_bsum[256];                      // 196 used
__device__ int     g_csr_src[N_EDGES];
__device__ float   g_norm[N_NODES];
// fp16 message buffers, one per hop slot: [N][128] halfs = 16 uint4 per node
// invariant: msg_s[m] = feats_s[m] * nm[m]
__device__ uint4   g_msg0[(size_t)N_NODES * 16];
__device__ uint4   g_msg1[(size_t)N_NODES * 16];
__device__ uint4   g_msg2[(size_t)N_NODES * 16];
__device__ uint4   g_msg3[(size_t)N_NODES * 16];
// W transposed to [n][k], fp16
__device__ __align__(16) __half g_Wh1[128 * 512];
__device__ __align__(16) __half g_Wh2[128 * 512];

__device__ __forceinline__ void add8(float* a, uint4 u) {
    float2 p0 = __half22float2(*(__half2*)&u.x);
    float2 p1 = __half22float2(*(__half2*)&u.y);
    float2 p2 = __half22float2(*(__half2*)&u.z);
    float2 p3 = __half22float2(*(__half2*)&u.w);
    a[0] += p0.x; a[1] += p0.y; a[2] += p1.x; a[3] += p1.y;
    a[4] += p2.x; a[5] += p2.y; a[6] += p3.x; a[7] += p3.y;
}
__device__ __forceinline__ uint4 h2add8(uint4 a, uint4 b) {
    uint4 r;
    *(__half2*)&r.x = __hadd2(*(__half2*)&a.x, *(__half2*)&b.x);
    *(__half2*)&r.y = __hadd2(*(__half2*)&a.y, *(__half2*)&b.y);
    *(__half2*)&r.z = __hadd2(*(__half2*)&a.z, *(__half2*)&b.z);
    *(__half2*)&r.w = __hadd2(*(__half2*)&a.w, *(__half2*)&b.w);
    return r;
}
__device__ __forceinline__ uint4 pack8(const float* a, float s) {
    __half2 h0 = __floats2half2_rn(a[0] * s, a[1] * s);
    __half2 h1 = __floats2half2_rn(a[2] * s, a[3] * s);
    __half2 h2 = __floats2half2_rn(a[4] * s, a[5] * s);
    __half2 h3 = __floats2half2_rn(a[6] * s, a[7] * s);
    uint4 u;
    u.x = *(uint32_t*)&h0; u.y = *(uint32_t*)&h1;
    u.z = *(uint32_t*)&h2; u.w = *(uint32_t*)&h3;
    return u;
}
__device__ __forceinline__ uint32_t s2u(const void* p) {
    uint32_t a;
    asm("{ .reg .u64 t; cvta.to.shared.u64 t, %1; cvt.u32.u64 %0, t; }" : "=r"(a) : "l"(p));
    return a;
}
__device__ __forceinline__ void ldsm4(uint32_t* r, uint32_t addr) {
    asm volatile("ldmatrix.sync.aligned.m8n8.x4.shared.b16 {%0,%1,%2,%3}, [%4];"
                 : "=r"(r[0]), "=r"(r[1]), "=r"(r[2]), "=r"(r[3]) : "r"(addr));
}
__device__ __forceinline__ void mma16816(float* c, const uint32_t* a, const uint32_t* b) {
    asm volatile(
        "mma.sync.aligned.m16n8k16.row.col.f32.f16.f16.f32 "
        "{%0,%1,%2,%3}, {%4,%5,%6,%7}, {%8,%9}, {%0,%1,%2,%3};"
        : "+f"(c[0]), "+f"(c[1]), "+f"(c[2]), "+f"(c[3])
        : "r"(a[0]), "r"(a[1]), "r"(a[2]), "r"(a[3]), "r"(b[0]), "r"(b[1]));
}

// ---------------- CSR build ----------------
__global__ void k_hist(const int* __restrict__ dst) {
    int e = blockIdx.x * blockDim.x + threadIdx.x;
    if (e < N_EDGES) atomicAdd(&g_cnt[dst[e]], 1);
}

#define SCAN_T 512
#define SCAN_NB ((N_NODES + SCAN_T - 1) / SCAN_T)   // 196

__global__ void k_scan1() {
    __shared__ int sh[SCAN_T];
    int tid = threadIdx.x;
    int gi  = blockIdx.x * SCAN_T + tid;
    int v   = (gi < N_NODES) ? g_cnt[gi] : 0;
    if (gi < N_NODES) {
        int d = v < 1 ? 1 : v;
        g_norm[gi] = rsqrtf((float)d);
    }
    sh[tid] = v;
    __syncthreads();
    for (int off = 1; off < SCAN_T; off <<= 1) {
        int t = (tid >= off) ? sh[tid - off] : 0;
        __syncthreads();
        sh[tid] += t;
        __syncthreads();
    }
    if (gi < N_NODES) g_row[gi] = sh[tid] - v;
    if (tid == SCAN_T - 1) g_bsum[blockIdx.x] = sh[tid];
}

__global__ void k_scan3() {
    __shared__ int s_off;
    int tid = threadIdx.x;
    int bid = blockIdx.x;
    if (tid < 32) {
        int s = 0;
        for (int i = tid; i < bid; i += 32) s += g_bsum[i];
#pragma unroll
        for (int o = 16; o > 0; o >>= 1) s += __shfl_down_sync(0xFFFFFFFF, s, o);
        if (tid == 0) s_off = s;
    }
    __syncthreads();
    int gi = bid * SCAN_T + tid;
    if (gi < N_NODES) {
        int v = g_row[gi] + s_off;
        g_row[gi] = v;
        g_cur[gi] = v;
    }
    if (gi == 0) g_row[N_NODES] = N_EDGES;
}

__global__ void k_fill(const int* __restrict__ src, const int* __restrict__ dst) {
    int e = blockIdx.x * blockDim.x + threadIdx.x;
    if (e < N_EDGES) {
        int d   = dst[e];
        int pos = atomicAdd(&g_cur[d], 1);
        g_csr_src[pos] = src[e];
    }
}

// ---------------- W prep: transpose to [n][k], fp16 ----------------
__global__ void k_prepW(const float* __restrict__ W1, const float* __restrict__ W2) {
    int idx = blockIdx.x * blockDim.x + threadIdx.x;   // 512*128
    if (idx >= 512 * 128) return;
    int k = idx >> 7;
    int n = idx & 127;
    g_Wh1[n * 512 + k] = __float2half_rn(W1[idx]);
    g_Wh2[n * 512 + k] = __float2half_rn(W2[idx]);
}

// ---------------- copy x -> msg0 = x * nm (fp16) ----------------
__global__ void k_copy0(const float4* __restrict__ x4) {
    int idx = blockIdx.x * blockDim.x + threadIdx.x;   // N*16
    int node = idx >> 4;
    int q    = idx & 15;
    float4 v0 = x4[node * 32 + q * 2];
    float4 v1 = x4[node * 32 + q * 2 + 1];
    float a[8] = {v0.x, v0.y, v0.z, v0.w, v1.x, v1.y, v1.z, v1.w};
    g_msg0[(size_t)node * 16 + q] = pack8(a, g_norm[node]);
}

// ---------------- aggregation: half-warp per node, fp16 quad-tree sums ----------------
// out[m] = (sum_{e in row m} in[src]) * nm[m]^2       (R9-proven layout)
__global__ __launch_bounds__(256) void k_agg(const uint4* __restrict__ tin,
                                             uint4* __restrict__ tout) {
    int hw   = threadIdx.x >> 4;                       // 0..15
    int hl   = threadIdx.x & 15;
    int node = blockIdx.x * 16 + hw;                   // grid = 6250, exact

    int beg = g_row[node];
    int end = g_row[node + 1];

    float acc[8] = {0.f, 0.f, 0.f, 0.f, 0.f, 0.f, 0.f, 0.f};

    // head: advance to 4-aligned edge index
    int e = beg;
    int alignEnd = (beg + 3) & ~3;
    if (alignEnd > end) alignEnd = end;
    for (; e < alignEnd; e++) {
        int s = __ldg(&g_csr_src[e]);
        add8(acc, tin[(size_t)s * 16 + hl]);
    }
    // main: 4 edges per iter, vector index load + fp16 quad tree
    for (; e + 4 <= end; e += 4) {
        int4 s4 = *(const int4*)&g_csr_src[e];         // 16B aligned
        uint4 u0 = tin[(size_t)s4.x * 16 + hl];
        uint4 u1 = tin[(size_t)s4.y * 16 + hl];
        uint4 u2 = tin[(size_t)s4.z * 16 + hl];
        uint4 u3 = tin[(size_t)s4.w * 16 + hl];
        uint4 q = h2add8(h2add8(u0, u1), h2add8(u2, u3));
        add8(acc, q);
    }
    // tail
    for (; e < end; e++) {
        int s = __ldg(&g_csr_src[e]);
        add8(acc, tin[(size_t)s * 16 + hl]);
    }

    float nm = g_norm[node];
    tout[(size_t)node * 16 + hl] = pack8(acc, nm * nm);
}

// ---------------- HMMA GEMM: relu((msgcat[M,512] @ W) / nm + b) ----------------
// Block tile 128x128, 256 threads = 4(M) x 2(N) warps, each warp 32x64.
// Single fp16 W (no lo-correction): 1 MMA per logical product.
#define ASTRIDE 80
__global__ __launch_bounds__(256) void k_gemm_mma(const __half* __restrict__ m0,
                                                  const __half* __restrict__ m1,
                                                  const __half* __restrict__ m2,
                                                  const __half* __restrict__ m3,
                                                  const __half* __restrict__ Wh,
                                                  const float* __restrict__ bias,
                                                  float* __restrict__ out,
                                                  int mode) {
    __shared__ __align__(16) char sA [128 * ASTRIDE];
    __shared__ __align__(16) char sBh[128 * ASTRIDE];
    __shared__ float sBias[128];

    int tid  = threadIdx.x;
    int lane = tid & 31;
    int wid  = tid >> 5;
    int wm   = wid & 3;
    int wn   = wid >> 2;
    int row0 = blockIdx.x * 128;

    if (tid < 128) sBias[tid] = bias[tid];

    uint32_t aA = s2u(sA), aBh = s2u(sBh);

    uint32_t aRow = (lane & 7) + ((lane >> 3) & 1) * 8;
    uint32_t aCol = (lane >> 4) * 16;
    uint32_t bRow = (lane & 7) + (lane >> 4) * 8;
    uint32_t bCol = ((lane >> 3) & 1) * 16;

    float acc[2][8][4];
#pragma unroll
    for (int mt = 0; mt < 2; mt++)
#pragma unroll
        for (int nt = 0; nt < 8; nt++)
#pragma unroll
            for (int q = 0; q < 4; q++) acc[mt][nt][q] = 0.f;

    int fr0 = tid >> 2,         fq0 = tid & 3;
    int fr1 = (tid + 256) >> 2, fq1 = (tid + 256) & 3;
    int grow0 = row0 + fr0; if (grow0 > N_NODES - 1) grow0 = N_NODES - 1;
    int grow1 = row0 + fr1; if (grow1 > N_NODES - 1) grow1 = N_NODES - 1;

    for (int kc = 0; kc < 16; kc++) {
        const __half* M = (kc < 8) ? ((kc < 4) ? m0 : m1) : ((kc < 12) ? m2 : m3);
        int ko = (kc & 3) * 32;
        {
            uint4 v0 = *((const uint4*)(M + (size_t)grow0 * FDIM + ko) + fq0);
            uint4 v1 = *((const uint4*)(M + (size_t)grow1 * FDIM + ko) + fq1);
            *(uint4*)(sA + fr0 * ASTRIDE + fq0 * 16) = v0;
            *(uint4*)(sA + fr1 * ASTRIDE + fq1 * 16) = v1;
        }
#pragma unroll
        for (int jj = 0; jj < 2; jj++) {
            int f = jj * 256 + tid;
            int r = f >> 2;
            int s = f & 3;
            size_t go = ((size_t)r * 512 + kc * 32) * 2 + s * 16;
            *(uint4*)(sBh + r * ASTRIDE + s * 16) = *(const uint4*)((const char*)Wh + go);
        }
        __syncthreads();

#pragma unroll
        for (int ks = 0; ks < 2; ks++) {
            uint32_t kb = ks * 32;
            uint32_t ah[2][4];
#pragma unroll
            for (int mt = 0; mt < 2; mt++) {
                uint32_t row = wm * 32 + mt * 16 + aRow;
                ldsm4(ah[mt], aA + row * ASTRIDE + kb + aCol);
            }
            uint32_t bh[4][4];
#pragma unroll
            for (int np = 0; np < 4; np++) {
                uint32_t row = wn * 64 + np * 16 + bRow;
                ldsm4(bh[np], aBh + row * ASTRIDE + kb + bCol);
            }
#pragma unroll
            for (int mt = 0; mt < 2; mt++)
#pragma unroll
                for (int nt = 0; nt < 8; nt++) {
                    const uint32_t* fh = &bh[nt >> 1][(nt & 1) * 2];
                    mma16816(acc[mt][nt], ah[mt], fh);
                }
        }
        __syncthreads();
    }

    // --- epilogue: unscale by 1/nm, bias, relu, fused stores ---
    int qr = lane >> 2;
    int qc = lane & 3;
#pragma unroll
    for (int mt = 0; mt < 2; mt++) {
#pragma unroll
        for (int half = 0; half < 2; half++) {
            int m = row0 + wm * 32 + mt * 16 + qr + half * 8;
            if (m >= N_NODES) continue;
            float nm  = g_norm[m];
            float rnm = 1.0f / nm;
            uint32_t* mrow = (uint32_t*)g_msg0 + (size_t)m * 64;
            float*    orow = out + (size_t)m * FDIM;
#pragma unroll
            for (int nt = 0; nt < 8; nt++) {
                int col = wn * 64 + nt * 8 + qc * 2;
                float c0 = acc[mt][nt][half * 2 + 0] * rnm + sBias[col];
                float c1 = acc[mt][nt][half * 2 + 1] * rnm + sBias[col + 1];
                c0 = c0 > 0.f ? c0 : 0.f;
                c1 = c1 > 0.f ? c1 : 0.f;
                if (mode == 1) {
                    __half2 t = __floats2half2_rn(c0 * nm, c1 * nm);
                    mrow[col >> 1] = *(uint32_t*)&t;   // msg0 for layer 2
                } else {
                    *(float2*)(orow + col) = make_float2(c0, c1);
                }
            }
        }
    }
}

// ---------------- launch ----------------
extern "C" void kernel_launch(void* const* d_in, const int* in_sizes, int n_in,
                              void* d_out, int out_size) {
    const float* x  = (const float*)d_in[0];
    const int*   ei = (const int*)  d_in[1];
    const float* W1 = (const float*)d_in[2];
    const float* b1 = (const float*)d_in[3];
    const float* W2 = (const float*)d_in[4];
    const float* b2 = (const float*)d_in[5];
    float* out = (float*)d_out;

    const int* src = ei;
    const int* dst = ei + N_EDGES;

    const int TB = 256;
    const int gE = (N_EDGES + TB - 1) / TB;

    __half *wh1, *wh2;
    uint4 *p0, *p1, *p2, *p3;
    int* cnt;
    cudaGetSymbolAddress((void**)&wh1, g_Wh1);
    cudaGetSymbolAddress((void**)&wh2, g_Wh2);
    cudaGetSymbolAddress((void**)&p0, g_msg0);
    cudaGetSymbolAddress((void**)&p1, g_msg1);
    cudaGetSymbolAddress((void**)&p2, g_msg2);
    cudaGetSymbolAddress((void**)&p3, g_msg3);
    cudaGetSymbolAddress((void**)&cnt, g_cnt);

    // --- CSR-by-dst build + norms + W prep ---
    cudaMemsetAsync(cnt, 0, N_NODES * sizeof(int));
    k_hist<<<gE, TB>>>(dst);
    k_scan1<<<SCAN_NB, SCAN_T>>>();       // also computes g_norm
    k_scan3<<<SCAN_NB, SCAN_T>>>();       // block-prefix computed in-block
    k_fill<<<gE, TB>>>(src, dst);
    k_prepW<<<(512 * 128) / TB, TB>>>(W1, W2);

    const int gAgg  = N_NODES / 16;                     // 6250 (half-warp per node)
    const int gCpy  = (N_NODES * 16) / TB;              // 6250
    const int gGemm = (N_NODES + 127) / 128;            // 782

    // --- layer 1 ---
    k_copy0<<<gCpy, TB>>>((const float4*)x);
    k_agg<<<gAgg, TB>>>(p0, p1);
    k_agg<<<gAgg, TB>>>(p1, p2);
    k_agg<<<gAgg, TB>>>(p2, p3);
    k_gemm_mma<<<gGemm, TB>>>((const __half*)p0, (const __half*)p1, (const __half*)p2,
                              (const __half*)p3, wh1, b1, nullptr, 1);

    // --- layer 2 ---
    k_agg<<<gAgg, TB>>>(p0, p1);
    k_agg<<<gAgg, TB>>>(p1, p2);
    k_agg<<<gAgg, TB>>>(p2, p3);
    k_gemm_mma<<<gGemm, TB>>>((const __half*)p0, (const __half*)p1, (const __half*)p2,
                              (const __half*)p3, wh2, b2, out, 2);
}